// round 2
// baseline (speedup 1.0000x reference)
#include <cuda_runtime.h>

#define N_NODES 100000
#define N_EDGES 3200000
#define F_IN    1433
#define F_HID   16
#define F_OUT   7

#define KPAD     1440            // F_IN padded to multiple of 32 (zero-filled)
#define G1_GRID  296             // 148 SMs x 2 blocks (smem-limited occupancy)
#define NCHUNK   (N_NODES / 4)   // 4-row warp chunks

// ---------------- scratch (device globals; no allocation allowed) ----------
__device__ float g_h1  [N_NODES * F_HID];   // 6.4 MB  (ns-scaled X @ W1)
__device__ float g_agg1[N_NODES * F_HID];   // 6.4 MB  scatter target layer 1
__device__ float g_h2  [N_NODES * 8];       // 3.2 MB  (padded to 8 for v4 red)
__device__ float g_agg2[N_NODES * 8];       // 3.2 MB  scatter target layer 2
__device__ float g_degout[N_NODES];
__device__ float g_degin [N_NODES];
__device__ float g_ns[N_NODES];
__device__ float g_nd[N_NODES];

__device__ __forceinline__ void red_add_v4(float* p, float4 v) {
    asm volatile("red.global.add.v4.f32 [%0], {%1, %2, %3, %4};"
                 :: "l"(p), "f"(v.x), "f"(v.y), "f"(v.z), "f"(v.w)
                 : "memory");
}

// ---- packed f32x2 helpers (sm_103a FFMA2 — PTX-only form) ------------------
__device__ __forceinline__ unsigned long long fma2(unsigned long long a,
                                                   unsigned long long b,
                                                   unsigned long long c) {
    unsigned long long d;
    asm("fma.rn.f32x2 %0, %1, %2, %3;" : "=l"(d) : "l"(a), "l"(b), "l"(c));
    return d;
}
__device__ __forceinline__ unsigned long long add2(unsigned long long a,
                                                   unsigned long long b) {
    unsigned long long d;
    asm("add.rn.f32x2 %0, %1, %2;" : "=l"(d) : "l"(a), "l"(b));
    return d;
}
__device__ __forceinline__ unsigned long long splat2(float x) {
    unsigned long long d;
    asm("mov.b64 %0, {%1, %1};" : "=l"(d) : "f"(x));
    return d;
}
__device__ __forceinline__ float2 unpack2(unsigned long long v) {
    float2 r;
    asm("mov.b64 {%0, %1}, %2;" : "=f"(r.x), "=f"(r.y) : "l"(v));
    return r;
}

// ---------------- zeroing (graph-replay safe) -------------------------------
__global__ void zero_kernel() {
    int t = blockIdx.x * blockDim.x + threadIdx.x;
    float4 z = make_float4(0.f, 0.f, 0.f, 0.f);
    if (t < N_NODES * F_HID / 4) ((float4*)g_agg1)[t] = z;
    if (t < N_NODES * 8 / 4)     ((float4*)g_agg2)[t] = z;
    if (t < N_NODES) { g_degout[t] = 0.f; g_degin[t] = 0.f; }
}

// ---------------- degrees + norms -------------------------------------------
__global__ void degree_kernel(const int* __restrict__ src,
                              const int* __restrict__ dst) {
    int e = blockIdx.x * blockDim.x + threadIdx.x;
    if (e >= N_EDGES) return;
    atomicAdd(&g_degout[src[e]], 1.0f);
    atomicAdd(&g_degin [dst[e]], 1.0f);
}

__global__ void norm_kernel() {
    int n = blockIdx.x * blockDim.x + threadIdx.x;
    if (n >= N_NODES) return;
    g_ns[n] = rsqrtf(fmaxf(g_degout[n], 1.0f));
    g_nd[n] = rsqrtf(fmaxf(g_degin [n], 1.0f));
}

// ---------------- GEMM1: h1 = diag(ns) * X @ W1  [100000 x 1433 x 16] -------
// W1 lives in smem, transposed & pair-packed: sWp[p][k] = {W[k][2p], W[k][2p+1]},
// k-contiguous so the per-k LDS.64 across lanes is conflict-free. Each warp
// owns 4 rows; lanes split K; accumulation in packed f32x2 (32 FFMA2 per
// warp-k-step instead of 64 FFMA). K padded to 1440 with zeros: no tail branch.
__global__ __launch_bounds__(256) void gemm1_kernel(const float* __restrict__ X,
                                                    const float* __restrict__ W) {
    extern __shared__ unsigned long long sWp[];   // [8][KPAD] packed float2

    // stage W: read as float2 (coalesced), write transposed
    const float2* Wv = (const float2*)W;          // Wv[k*8 + p]
    for (int idx = threadIdx.x; idx < 8 * KPAD; idx += 256) {
        int k = idx >> 3, p = idx & 7;
        float2 v = (k < F_IN) ? Wv[k * 8 + p] : make_float2(0.f, 0.f);
        unsigned long long pk;
        asm("mov.b64 %0, {%1, %2};" : "=l"(pk) : "f"(v.x), "f"(v.y));
        sWp[p * KPAD + k] = pk;
    }
    __syncthreads();

    int lane = threadIdx.x & 31;
    int gw   = blockIdx.x * 8 + (threadIdx.x >> 5);

    for (int chunk = gw; chunk < NCHUNK; chunk += G1_GRID * 8) {
        long m0 = (long)chunk * 4;
        const float* Xr = X + m0 * F_IN;

        unsigned long long acc[4][8];
#pragma unroll
        for (int i = 0; i < 4; i++)
#pragma unroll
            for (int p = 0; p < 8; p++) acc[i][p] = 0ull;

#pragma unroll 1
        for (int k0 = 0; k0 < KPAD; k0 += 32) {
            int k = k0 + lane;
            unsigned long long xx[4];
            if (k < F_IN) {
#pragma unroll
                for (int i = 0; i < 4; i++) xx[i] = splat2(Xr[(long)i * F_IN + k]);
            } else {
#pragma unroll
                for (int i = 0; i < 4; i++) xx[i] = 0ull;
            }
#pragma unroll
            for (int p = 0; p < 8; p++) {
                unsigned long long w = sWp[p * KPAD + k];   // zero in pad region
#pragma unroll
                for (int i = 0; i < 4; i++) acc[i][p] = fma2(xx[i], w, acc[i][p]);
            }
        }

        // butterfly reduce across lanes (packed adds)
#pragma unroll
        for (int off = 16; off > 0; off >>= 1)
#pragma unroll
            for (int i = 0; i < 4; i++)
#pragma unroll
                for (int p = 0; p < 8; p++)
                    acc[i][p] = add2(acc[i][p],
                                     __shfl_xor_sync(0xffffffffu, acc[i][p], off));

        if (lane == 0) {
#pragma unroll
            for (int i = 0; i < 4; i++) {
                float s = g_ns[m0 + i];
                float2* o = (float2*)(g_h1 + (m0 + i) * F_HID);
#pragma unroll
                for (int p = 0; p < 8; p++) {
                    float2 v = unpack2(acc[i][p]);
                    o[p] = make_float2(v.x * s, v.y * s);
                }
            }
        }
    }
}

// ---------------- scatter 1: agg1[dst] += h1[src]  (16 wide) ----------------
__global__ void scatter1_kernel(const int* __restrict__ src,
                                const int* __restrict__ dst) {
    int e = blockIdx.x * blockDim.x + threadIdx.x;
    if (e >= N_EDGES) return;
    int s = src[e], d = dst[e];
    const float4* hs = (const float4*)(g_h1 + (size_t)s * F_HID);
    float4 a = hs[0], b = hs[1], c = hs[2], f = hs[3];
    float* base = g_agg1 + (size_t)d * F_HID;
    red_add_v4(base + 0,  a);
    red_add_v4(base + 4,  b);
    red_add_v4(base + 8,  c);
    red_add_v4(base + 12, f);
}

// ---------------- GEMM2: h2 = diag(ns) * relu(agg1*nd + b1) @ W2 ------------
__global__ void gemm2_kernel(const float* __restrict__ b1,
                             const float* __restrict__ W2) {
    __shared__ float sW[F_HID * F_OUT];
    __shared__ float sb[F_HID];
    if (threadIdx.x < F_HID * F_OUT) sW[threadIdx.x] = W2[threadIdx.x];
    if (threadIdx.x < F_HID)         sb[threadIdx.x] = b1[threadIdx.x];
    __syncthreads();

    int n = blockIdx.x * blockDim.x + threadIdx.x;
    if (n >= N_NODES) return;

    float ndv = g_nd[n], nsv = g_ns[n];
    const float4* a4 = (const float4*)(g_agg1 + (size_t)n * F_HID);
    float x[F_HID];
#pragma unroll
    for (int q = 0; q < 4; q++) {
        float4 v = a4[q];
        x[q*4+0] = v.x; x[q*4+1] = v.y; x[q*4+2] = v.z; x[q*4+3] = v.w;
    }
    float o[F_OUT];
#pragma unroll
    for (int j = 0; j < F_OUT; j++) o[j] = 0.f;
#pragma unroll
    for (int i = 0; i < F_HID; i++) {
        float xi = fmaxf(fmaf(x[i], ndv, sb[i]), 0.f) * nsv;
#pragma unroll
        for (int j = 0; j < F_OUT; j++) o[j] = fmaf(xi, sW[i * F_OUT + j], o[j]);
    }
    float4* hp = (float4*)(g_h2 + (size_t)n * 8);
    hp[0] = make_float4(o[0], o[1], o[2], o[3]);
    hp[1] = make_float4(o[4], o[5], o[6], 0.f);   // pad lane stays 0
}

// ---------------- scatter 2: agg2[dst] += h2[src]  (8 wide, padded) ---------
__global__ void scatter2_kernel(const int* __restrict__ src,
                                const int* __restrict__ dst) {
    int e = blockIdx.x * blockDim.x + threadIdx.x;
    if (e >= N_EDGES) return;
    int s = src[e], d = dst[e];
    const float4* hs = (const float4*)(g_h2 + (size_t)s * 8);
    float4 a = hs[0], b = hs[1];
    float* base = g_agg2 + (size_t)d * 8;
    red_add_v4(base + 0, a);
    red_add_v4(base + 4, b);
}

// ---------------- finalize: out = agg2*nd + b2 -------------------------------
__global__ void final_kernel(const float* __restrict__ b2,
                             float* __restrict__ out) {
    int t = blockIdx.x * blockDim.x + threadIdx.x;
    if (t >= N_NODES * F_OUT) return;
    int n = t / F_OUT;
    int j = t - n * F_OUT;
    out[t] = fmaf(g_agg2[(size_t)n * 8 + j], g_nd[n], b2[j]);
}

// ---------------- launch ------------------------------------------------------
extern "C" void kernel_launch(void* const* d_in, const int* in_sizes, int n_in,
                              void* d_out, int out_size) {
    const float* X   = (const float*)d_in[0];
    const int*   src = (const int*)  d_in[1];
    const int*   dst = (const int*)  d_in[2];
    const float* W1  = (const float*)d_in[3];
    const float* b1  = (const float*)d_in[4];
    const float* W2  = (const float*)d_in[5];
    const float* b2  = (const float*)d_in[6];
    float* out = (float*)d_out;

    const int g1_smem = 8 * KPAD * 8;   // 92160 bytes
    static int attr_done = 0;
    if (!attr_done) {   // idempotent host-side attribute, not a capture op
        cudaFuncSetAttribute(gemm1_kernel,
                             cudaFuncAttributeMaxDynamicSharedMemorySize, g1_smem);
        attr_done = 1;
    }

    zero_kernel  <<<(N_NODES * F_HID / 4 + 255) / 256, 256>>>();
    degree_kernel<<<N_EDGES / 256, 256>>>(src, dst);
    norm_kernel  <<<(N_NODES + 255) / 256, 256>>>();
    gemm1_kernel <<<G1_GRID, 256, g1_smem>>>(X, W1);
    scatter1_kernel<<<N_EDGES / 256, 256>>>(src, dst);
    gemm2_kernel <<<(N_NODES + 255) / 256, 256>>>(b1, W2);
    scatter2_kernel<<<N_EDGES / 256, 256>>>(src, dst);
    final_kernel <<<(N_NODES * F_OUT + 255) / 256, 256>>>(b2, out);
}

// round 3
// speedup vs baseline: 1.3008x; 1.3008x over previous
#include <cuda_runtime.h>

#define N_NODES 100000
#define N_EDGES 3200000
#define F_IN    1433
#define F_HID   16
#define F_OUT   7

#define KPAD     1472            // F_IN padded to multiple of 64 (zero-filled)
#define G1_GRID  296             // 148 SMs x 2 blocks (smem-limited occupancy)
#define NCHUNK   (N_NODES / 4)   // 4-row warp chunks

// ---------------- scratch (device globals; no allocation allowed) ----------
__device__ float g_h1  [N_NODES * F_HID];   // 6.4 MB  (ns-scaled X @ W1)
__device__ float g_agg1[N_NODES * F_HID];   // 6.4 MB  scatter target layer 1
__device__ float g_h2  [N_NODES * 8];       // 3.2 MB  (padded to 8 for v4 red)
__device__ float g_agg2[N_NODES * 8];       // 3.2 MB  scatter target layer 2
__device__ float g_degout[N_NODES];
__device__ float g_degin [N_NODES];
__device__ float g_ns[N_NODES];
__device__ float g_nd[N_NODES];

__device__ __forceinline__ void red_add_v4(float* p, float4 v) {
    asm volatile("red.global.add.v4.f32 [%0], {%1, %2, %3, %4};"
                 :: "l"(p), "f"(v.x), "f"(v.y), "f"(v.z), "f"(v.w)
                 : "memory");
}

// ---- packed f32x2 helpers (sm_103a FFMA2 — PTX-only form) ------------------
__device__ __forceinline__ unsigned long long fma2(unsigned long long a,
                                                   unsigned long long b,
                                                   unsigned long long c) {
    unsigned long long d;
    asm("fma.rn.f32x2 %0, %1, %2, %3;" : "=l"(d) : "l"(a), "l"(b), "l"(c));
    return d;
}
__device__ __forceinline__ unsigned long long add2(unsigned long long a,
                                                   unsigned long long b) {
    unsigned long long d;
    asm("add.rn.f32x2 %0, %1, %2;" : "=l"(d) : "l"(a), "l"(b));
    return d;
}
__device__ __forceinline__ unsigned long long splat2(float x) {
    unsigned long long d;
    asm("mov.b64 %0, {%1, %1};" : "=l"(d) : "f"(x));
    return d;
}
__device__ __forceinline__ float2 unpack2(unsigned long long v) {
    float2 r;
    asm("mov.b64 {%0, %1}, %2;" : "=f"(r.x), "=f"(r.y) : "l"(v));
    return r;
}
__device__ __forceinline__ float ldcs(const float* p) {
    float v;
    asm("ld.global.cs.f32 %0, [%1];" : "=f"(v) : "l"(p));
    return v;
}

// ---------------- zeroing (graph-replay safe) -------------------------------
__global__ void zero_kernel() {
    int t = blockIdx.x * blockDim.x + threadIdx.x;
    float4 z = make_float4(0.f, 0.f, 0.f, 0.f);
    if (t < N_NODES * F_HID / 4) ((float4*)g_agg1)[t] = z;
    if (t < N_NODES * 8 / 4)     ((float4*)g_agg2)[t] = z;
    if (t < N_NODES) { g_degout[t] = 0.f; g_degin[t] = 0.f; }
}

// ---------------- degrees + norms -------------------------------------------
__global__ void degree_kernel(const int* __restrict__ src,
                              const int* __restrict__ dst) {
    int e = blockIdx.x * blockDim.x + threadIdx.x;
    if (e >= N_EDGES) return;
    atomicAdd(&g_degout[src[e]], 1.0f);
    atomicAdd(&g_degin [dst[e]], 1.0f);
}

__global__ void norm_kernel() {
    int n = blockIdx.x * blockDim.x + threadIdx.x;
    if (n >= N_NODES) return;
    g_ns[n] = rsqrtf(fmaxf(g_degout[n], 1.0f));
    g_nd[n] = rsqrtf(fmaxf(g_degin [n], 1.0f));
}

// ---------------- GEMM1: h1 = diag(ns) * X @ W1  [100000 x 1433 x 16] -------
// W1 in smem, transposed + pair-packed (conflict-free LDS.64). Each warp owns
// 4 rows; lanes split K. Software-pipelined: while computing 64 k-values, the
// next 64 are prefetched into registers (8 independent LDG.cs in flight per
// warp) so DRAM latency is covered despite 16-warp occupancy.
__global__ __launch_bounds__(256) void gemm1_kernel(const float* __restrict__ X,
                                                    const float* __restrict__ W) {
    extern __shared__ unsigned long long sWp[];   // [8][KPAD] packed float2

    // stage W: read as float2 (coalesced), write transposed
    const float2* Wv = (const float2*)W;          // Wv[k*8 + p]
    for (int idx = threadIdx.x; idx < 8 * KPAD; idx += 256) {
        int k = idx >> 3, p = idx & 7;
        float2 v = (k < F_IN) ? Wv[k * 8 + p] : make_float2(0.f, 0.f);
        unsigned long long pk;
        asm("mov.b64 %0, {%1, %2};" : "=l"(pk) : "f"(v.x), "f"(v.y));
        sWp[p * KPAD + k] = pk;
    }
    __syncthreads();

    int lane = threadIdx.x & 31;
    int gw   = blockIdx.x * 8 + (threadIdx.x >> 5);

    for (int chunk = gw; chunk < NCHUNK; chunk += G1_GRID * 8) {
        long m0 = (long)chunk * 4;
        const float* Xr = X + m0 * F_IN;

        unsigned long long acc[4][8];
#pragma unroll
        for (int i = 0; i < 4; i++)
#pragma unroll
            for (int p = 0; p < 8; p++) acc[i][p] = 0ull;

        float xa[4], xb[4], pa[4], pb[4];

        // preload k-block 0  (lane and lane+32)
        {
            int ka = lane, kb = lane + 32;
#pragma unroll
            for (int i = 0; i < 4; i++) {
                xa[i] = (ka < F_IN) ? ldcs(Xr + (long)i * F_IN + ka) : 0.f;
                xb[i] = (kb < F_IN) ? ldcs(Xr + (long)i * F_IN + kb) : 0.f;
            }
        }

#pragma unroll 1
        for (int k0 = 0; k0 < KPAD; k0 += 64) {
            // prefetch next 64-k block (8 independent LDGs issued up front)
            int kn = k0 + 64;
            if (kn < KPAD) {
                int ka = kn + lane, kb = kn + 32 + lane;
#pragma unroll
                for (int i = 0; i < 4; i++) {
                    pa[i] = (ka < F_IN) ? ldcs(Xr + (long)i * F_IN + ka) : 0.f;
                    pb[i] = (kb < F_IN) ? ldcs(Xr + (long)i * F_IN + kb) : 0.f;
                }
            }

            // compute sub-block A (k = k0 + lane)
            {
                int k = k0 + lane;
                unsigned long long xx[4];
#pragma unroll
                for (int i = 0; i < 4; i++) xx[i] = splat2(xa[i]);
#pragma unroll
                for (int p = 0; p < 8; p++) {
                    unsigned long long w = sWp[p * KPAD + k];
#pragma unroll
                    for (int i = 0; i < 4; i++) acc[i][p] = fma2(xx[i], w, acc[i][p]);
                }
            }
            // compute sub-block B (k = k0 + 32 + lane)
            {
                int k = k0 + 32 + lane;
                unsigned long long xx[4];
#pragma unroll
                for (int i = 0; i < 4; i++) xx[i] = splat2(xb[i]);
#pragma unroll
                for (int p = 0; p < 8; p++) {
                    unsigned long long w = sWp[p * KPAD + k];
#pragma unroll
                    for (int i = 0; i < 4; i++) acc[i][p] = fma2(xx[i], w, acc[i][p]);
                }
            }

#pragma unroll
            for (int i = 0; i < 4; i++) { xa[i] = pa[i]; xb[i] = pb[i]; }
        }

        // butterfly reduce across lanes (packed adds)
#pragma unroll
        for (int off = 16; off > 0; off >>= 1)
#pragma unroll
            for (int i = 0; i < 4; i++)
#pragma unroll
                for (int p = 0; p < 8; p++)
                    acc[i][p] = add2(acc[i][p],
                                     __shfl_xor_sync(0xffffffffu, acc[i][p], off));

        if (lane == 0) {
#pragma unroll
            for (int i = 0; i < 4; i++) {
                float s = g_ns[m0 + i];
                float2* o = (float2*)(g_h1 + (m0 + i) * F_HID);
#pragma unroll
                for (int p = 0; p < 8; p++) {
                    float2 v = unpack2(acc[i][p]);
                    o[p] = make_float2(v.x * s, v.y * s);
                }
            }
        }
    }
}

// ---------------- scatter 1: agg1[dst] += h1[src]  (16 wide) ----------------
__global__ void scatter1_kernel(const int* __restrict__ src,
                                const int* __restrict__ dst) {
    int e = blockIdx.x * blockDim.x + threadIdx.x;
    if (e >= N_EDGES) return;
    int s = src[e], d = dst[e];
    const float4* hs = (const float4*)(g_h1 + (size_t)s * F_HID);
    float4 a = hs[0], b = hs[1], c = hs[2], f = hs[3];
    float* base = g_agg1 + (size_t)d * F_HID;
    red_add_v4(base + 0,  a);
    red_add_v4(base + 4,  b);
    red_add_v4(base + 8,  c);
    red_add_v4(base + 12, f);
}

// ---------------- GEMM2: h2 = diag(ns) * relu(agg1*nd + b1) @ W2 ------------
__global__ void gemm2_kernel(const float* __restrict__ b1,
                             const float* __restrict__ W2) {
    __shared__ float sW[F_HID * F_OUT];
    __shared__ float sb[F_HID];
    if (threadIdx.x < F_HID * F_OUT) sW[threadIdx.x] = W2[threadIdx.x];
    if (threadIdx.x < F_HID)         sb[threadIdx.x] = b1[threadIdx.x];
    __syncthreads();

    int n = blockIdx.x * blockDim.x + threadIdx.x;
    if (n >= N_NODES) return;

    float ndv = g_nd[n], nsv = g_ns[n];
    const float4* a4 = (const float4*)(g_agg1 + (size_t)n * F_HID);
    float x[F_HID];
#pragma unroll
    for (int q = 0; q < 4; q++) {
        float4 v = a4[q];
        x[q*4+0] = v.x; x[q*4+1] = v.y; x[q*4+2] = v.z; x[q*4+3] = v.w;
    }
    float o[F_OUT];
#pragma unroll
    for (int j = 0; j < F_OUT; j++) o[j] = 0.f;
#pragma unroll
    for (int i = 0; i < F_HID; i++) {
        float xi = fmaxf(fmaf(x[i], ndv, sb[i]), 0.f) * nsv;
#pragma unroll
        for (int j = 0; j < F_OUT; j++) o[j] = fmaf(xi, sW[i * F_OUT + j], o[j]);
    }
    float4* hp = (float4*)(g_h2 + (size_t)n * 8);
    hp[0] = make_float4(o[0], o[1], o[2], o[3]);
    hp[1] = make_float4(o[4], o[5], o[6], 0.f);   // pad lane stays 0
}

// ---------------- scatter 2: agg2[dst] += h2[src]  (8 wide, padded) ---------
__global__ void scatter2_kernel(const int* __restrict__ src,
                                const int* __restrict__ dst) {
    int e = blockIdx.x * blockDim.x + threadIdx.x;
    if (e >= N_EDGES) return;
    int s = src[e], d = dst[e];
    const float4* hs = (const float4*)(g_h2 + (size_t)s * 8);
    float4 a = hs[0], b = hs[1];
    float* base = g_agg2 + (size_t)d * 8;
    red_add_v4(base + 0, a);
    red_add_v4(base + 4, b);
}

// ---------------- finalize: out = agg2*nd + b2 -------------------------------
__global__ void final_kernel(const float* __restrict__ b2,
                             float* __restrict__ out) {
    int t = blockIdx.x * blockDim.x + threadIdx.x;
    if (t >= N_NODES * F_OUT) return;
    int n = t / F_OUT;
    int j = t - n * F_OUT;
    out[t] = fmaf(g_agg2[(size_t)n * 8 + j], g_nd[n], b2[j]);
}

// ---------------- launch ------------------------------------------------------
extern "C" void kernel_launch(void* const* d_in, const int* in_sizes, int n_in,
                              void* d_out, int out_size) {
    const float* X   = (const float*)d_in[0];
    const int*   src = (const int*)  d_in[1];
    const int*   dst = (const int*)  d_in[2];
    const float* W1  = (const float*)d_in[3];
    const float* b1  = (const float*)d_in[4];
    const float* W2  = (const float*)d_in[5];
    const float* b2  = (const float*)d_in[6];
    float* out = (float*)d_out;

    const int g1_smem = 8 * KPAD * 8;   // 94208 bytes
    static int attr_done = 0;
    if (!attr_done) {   // idempotent host-side attribute, not a capture op
        cudaFuncSetAttribute(gemm1_kernel,
                             cudaFuncAttributeMaxDynamicSharedMemorySize, g1_smem);
        attr_done = 1;
    }

    zero_kernel  <<<(N_NODES * F_HID / 4 + 255) / 256, 256>>>();
    degree_kernel<<<N_EDGES / 256, 256>>>(src, dst);
    norm_kernel  <<<(N_NODES + 255) / 256, 256>>>();
    gemm1_kernel <<<G1_GRID, 256, g1_smem>>>(X, W1);
    scatter1_kernel<<<N_EDGES / 256, 256>>>(src, dst);
    gemm2_kernel <<<(N_NODES + 255) / 256, 256>>>(b1, W2);
    scatter2_kernel<<<N_EDGES / 256, 256>>>(src, dst);
    final_kernel <<<(N_NODES * F_OUT + 255) / 256, 256>>>(b2, out);
}